// round 2
// baseline (speedup 1.0000x reference)
#include <cuda_runtime.h>
#include <cstdint>

#define N_NODES 100000
#define N_EDGES 600000
#define D_IN    128
#define D_OUT   96
#define N_REL   4

// ---------------- scratch (static device globals; no allocs allowed) --------
__device__ float g_H1[(size_t)N_REL * N_NODES * D_IN];    // 204.8 MB
__device__ float g_out1[(size_t)N_NODES * D_IN];          // 51.2 MB
__device__ float g_H2[(size_t)N_REL * N_NODES * D_OUT];   // 153.6 MB
__device__ float g_norm[N_EDGES];
__device__ int   g_cnt[N_NODES * N_REL];

// ---------------- degree counting ------------------------------------------
__global__ void zero_cnt_kernel() {
    int i = blockIdx.x * blockDim.x + threadIdx.x;
    if (i < N_NODES * N_REL) g_cnt[i] = 0;
}

__global__ void count_kernel(const int* __restrict__ ei, const int* __restrict__ et) {
    int e = blockIdx.x * blockDim.x + threadIdx.x;
    if (e < N_EDGES) {
        int dst = ei[N_EDGES + e];
        atomicAdd(&g_cnt[dst * N_REL + et[e]], 1);
    }
}

__global__ void norm_kernel(const int* __restrict__ ei, const int* __restrict__ et) {
    int e = blockIdx.x * blockDim.x + threadIdx.x;
    if (e < N_EDGES) {
        int dst = ei[N_EDGES + e];
        int c = g_cnt[dst * N_REL + et[e]];
        g_norm[e] = 1.0f / (float)(c > 1 ? c : 1);
    }
}

// ---------------- batched GEMM: 128x128 tile, 8x8/thread, f32x2 FFMA2 -------
// grid.z = N_REL+1 batches: z<N_REL -> H[z] = A @ W[z]; z==N_REL -> out = A@root + b
// layer==1: A = A_ext (input x), H = g_H1, O = g_out1
// layer==2: A = g_out1 (device symbol, resolved DEVICE-side), H = g_H2, O = out_ext
__global__ __launch_bounds__(256, 2)
void gemm_batched(const float* __restrict__ A_ext, const float* __restrict__ W,
                  const float* __restrict__ root, const float* __restrict__ bias,
                  float* __restrict__ out_ext, int n, int dout, int layer)
{
    __shared__ float As[128 * 8];
    __shared__ float Bs[8 * 128];

    int batch = blockIdx.z;
    bool isRoot = (batch == N_REL);
    const float* B = isRoot ? root : (W + (size_t)batch * D_IN * dout);

    // CRITICAL: device-global addresses must be resolved in DEVICE code.
    const float* A  = (layer == 1) ? A_ext : g_out1;
    float* Hbuf     = (layer == 1) ? g_H1  : g_H2;
    float* Obuf     = (layer == 1) ? g_out1 : out_ext;
    float* dstbuf   = isRoot ? Obuf : (Hbuf + (size_t)batch * n * dout);

    int rowBase = blockIdx.y * 128;
    int tid = threadIdx.x;
    int tx = tid & 15;       // 16 col groups of 8
    int ty = tid >> 4;       // 16 row groups of 8

    // A tile load mapping: one float4 per thread
    int a_r = tid >> 1;          // 0..127
    int a_k = (tid & 1) * 4;     // 0 or 4
    // B tile load mapping: one float4 per thread
    int b_r = tid >> 5;          // 0..7
    int b_c = (tid & 31) * 4;    // 0..124

    unsigned long long acc[8][4];
#pragma unroll
    for (int i = 0; i < 8; i++)
#pragma unroll
        for (int j = 0; j < 4; j++) acc[i][j] = 0ULL;

    int grow_a = rowBase + a_r;

    for (int kk = 0; kk < D_IN; kk += 8) {
        float4 av = make_float4(0.f, 0.f, 0.f, 0.f);
        if (grow_a < n)
            av = *(const float4*)(A + (size_t)grow_a * D_IN + kk + a_k);
        *(float4*)(As + a_r * 8 + a_k) = av;

        float4 bv = make_float4(0.f, 0.f, 0.f, 0.f);
        if (b_c < dout)
            bv = *(const float4*)(B + (size_t)(kk + b_r) * dout + b_c);
        *(float4*)(Bs + b_r * 128 + b_c) = bv;

        __syncthreads();

#pragma unroll
        for (int k = 0; k < 8; k++) {
            union { float4 f; unsigned long long d[2]; } u0, u1;
            u0.f = *(float4*)(Bs + k * 128 + tx * 8);
            u1.f = *(float4*)(Bs + k * 128 + tx * 8 + 4);
            unsigned long long breg[4] = { u0.d[0], u0.d[1], u1.d[0], u1.d[1] };
#pragma unroll
            for (int i = 0; i < 8; i++) {
                unsigned ai = __float_as_uint(As[(ty * 8 + i) * 8 + k]);
                unsigned long long a2;
                asm("mov.b64 %0, {%1, %1};" : "=l"(a2) : "r"(ai));
#pragma unroll
                for (int j = 0; j < 4; j++) {
                    asm("fma.rn.f32x2 %0, %1, %2, %0;"
                        : "+l"(acc[i][j]) : "l"(a2), "l"(breg[j]));
                }
            }
        }
        __syncthreads();
    }

    // writeback
#pragma unroll
    for (int i = 0; i < 8; i++) {
        int grow = rowBase + ty * 8 + i;
        if (grow >= n) continue;
        float* rowp = dstbuf + (size_t)grow * dout;
#pragma unroll
        for (int j = 0; j < 4; j++) {
            int gcol = tx * 8 + j * 2;
            union { unsigned long long d; float f[2]; } u; u.d = acc[i][j];
            if (gcol < dout) {
                float v = u.f[0];
                if (isRoot) v += bias[gcol];
                rowp[gcol] = v;
            }
            if (gcol + 1 < dout) {
                float v = u.f[1];
                if (isRoot) v += bias[gcol + 1];
                rowp[gcol + 1] = v;
            }
        }
    }
}

// ---------------- edge scatter: one warp per edge, red.global.add.v4 --------
template <int DOUT>
__global__ void scatter_kernel(const int* __restrict__ ei, const int* __restrict__ et,
                               float* __restrict__ out_ext, int layer)
{
    int warp = blockIdx.x * (blockDim.x >> 5) + (threadIdx.x >> 5);
    int lane = threadIdx.x & 31;
    if (warp >= N_EDGES) return;

    const float* H = (layer == 1) ? g_H1 : g_H2;
    float* out = (layer == 1) ? g_out1 : out_ext;

    int src = ei[warp];
    int dst = ei[N_EDGES + warp];
    int t   = et[warp];
    float nm = g_norm[warp];

    if (lane < DOUT / 4) {
        const float4* hp = (const float4*)(H + ((size_t)t * N_NODES + src) * DOUT);
        float4 v = hp[lane];
        float* op = out + (size_t)dst * DOUT + lane * 4;
        asm volatile("red.global.add.v4.f32 [%0], {%1,%2,%3,%4};"
                     :: "l"(op), "f"(v.x * nm), "f"(v.y * nm),
                        "f"(v.z * nm), "f"(v.w * nm)
                     : "memory");
    }
}

// ---------------- ReLU in place on layer-1 output ---------------------------
__global__ void relu_kernel() {
    int i = blockIdx.x * blockDim.x + threadIdx.x;
    if (i < N_NODES * D_IN) {
        float v = g_out1[i];
        g_out1[i] = v > 0.f ? v : 0.f;
    }
}

// ---------------- launch ----------------------------------------------------
extern "C" void kernel_launch(void* const* d_in, const int* in_sizes, int n_in,
                              void* d_out, int out_size)
{
    const float* x     = (const float*)d_in[0];
    const int*   ei    = (const int*)d_in[1];
    const int*   et    = (const int*)d_in[2];
    const float* W1    = (const float*)d_in[3];
    const float* root1 = (const float*)d_in[4];
    const float* b1    = (const float*)d_in[5];
    const float* W2    = (const float*)d_in[6];
    const float* root2 = (const float*)d_in[7];
    const float* b2    = (const float*)d_in[8];
    float* out = (float*)d_out;

    // degree counts + per-edge norm (shared by both layers)
    zero_cnt_kernel<<<(N_NODES * N_REL + 255) / 256, 256>>>();
    count_kernel<<<(N_EDGES + 255) / 256, 256>>>(ei, et);
    norm_kernel<<<(N_EDGES + 255) / 256, 256>>>(ei, et);

    dim3 g1(1, (N_NODES + 127) / 128, N_REL + 1);
    // layer 1: H1[r] = x@W1[r]; out1 = x@root1 + b1
    gemm_batched<<<g1, 256>>>(x, W1, root1, b1, nullptr, N_NODES, D_IN, 1);
    scatter_kernel<D_IN><<<(N_EDGES + 7) / 8, 256>>>(ei, et, nullptr, 1);
    relu_kernel<<<(N_NODES * D_IN + 255) / 256, 256>>>();

    // layer 2: H2[r] = h@W2[r] (A resolved device-side to g_out1); out = h@root2 + b2
    gemm_batched<<<g1, 256>>>(nullptr, W2, root2, b2, out, N_NODES, D_OUT, 2);
    scatter_kernel<D_OUT><<<(N_EDGES + 7) / 8, 256>>>(ei, et, out, 2);
}

// round 5
// speedup vs baseline: 1.8276x; 1.8276x over previous
#include <cuda_runtime.h>
#include <cuda_bf16.h>
#include <cstdint>

#define N_NODES 100000
#define N_EDGES 600000
#define D_IN    128
#define D_OUT   96
#define N_REL   4

#define N_TILES  782                 // ceil(100000/128)
#define M_PAD    (N_TILES * 128)

#define ROW_BYTES 272                // 128 bf16 (256B) + 16B pad -> conflict-free ldmatrix
#define IMG_BYTES (128 * ROW_BYTES)  // 34816 per 128-row image
#define IMG_U4    (IMG_BYTES / 16)   // 2176

// ---------------- scratch (static device globals; no allocs allowed) --------
__device__ __align__(16) float g_H1[(size_t)N_REL * N_NODES * D_IN];    // 204.8 MB
__device__ __align__(16) float g_out1[(size_t)N_NODES * D_IN];          // 51.2 MB
__device__ __align__(16) float g_H2[(size_t)N_REL * N_NODES * D_OUT];   // 153.6 MB
__device__ float g_norm[N_EDGES];
__device__ int   g_cnt[N_NODES * N_REL];

// padded row-major bf16 hi/lo images
__device__ uint4 g_Ahi[(size_t)N_TILES * IMG_U4];   // [tile][row 128][k 128 + pad]
__device__ uint4 g_Alo[(size_t)N_TILES * IMG_U4];
__device__ uint4 g_B1hi[5 * IMG_U4];                // [batch][n 128][k 128 + pad]
__device__ uint4 g_B1lo[5 * IMG_U4];
__device__ uint4 g_B2hi[5 * IMG_U4];                // rows 96..127 stay zero
__device__ uint4 g_B2lo[5 * IMG_U4];

// ---------------- helpers ----------------------------------------------------
__device__ __forceinline__ uint32_t smem_u32(const void* p) {
    uint32_t a;
    asm("{ .reg .u64 t; cvta.to.shared.u64 t, %1; cvt.u32.u64 %0, t; }" : "=r"(a) : "l"(p));
    return a;
}

#define LDSM4(r, addr)                                                        \
    asm volatile("ldmatrix.sync.aligned.m8n8.x4.shared.b16 {%0,%1,%2,%3}, [%4];" \
                 : "=r"((r)[0]), "=r"((r)[1]), "=r"((r)[2]), "=r"((r)[3])     \
                 : "r"(addr))

#define MMA16816(d, a, b0, b1)                                                \
    asm volatile("mma.sync.aligned.m16n8k16.row.col.f32.bf16.bf16.f32 "       \
                 "{%0,%1,%2,%3},{%4,%5,%6,%7},{%8,%9},{%0,%1,%2,%3};"         \
                 : "+f"((d)[0]), "+f"((d)[1]), "+f"((d)[2]), "+f"((d)[3])     \
                 : "r"((a)[0]), "r"((a)[1]), "r"((a)[2]), "r"((a)[3]),        \
                   "r"(b0), "r"(b1))

// ---------------- degree counting -------------------------------------------
__global__ void zero_cnt_kernel() {
    int i = blockIdx.x * blockDim.x + threadIdx.x;
    if (i < N_NODES * N_REL) g_cnt[i] = 0;
}
__global__ void count_kernel(const int* __restrict__ ei, const int* __restrict__ et) {
    int e = blockIdx.x * blockDim.x + threadIdx.x;
    if (e < N_EDGES) atomicAdd(&g_cnt[ei[N_EDGES + e] * N_REL + et[e]], 1);
}
__global__ void norm_kernel(const int* __restrict__ ei, const int* __restrict__ et) {
    int e = blockIdx.x * blockDim.x + threadIdx.x;
    if (e < N_EDGES) {
        int c = g_cnt[ei[N_EDGES + e] * N_REL + et[e]];
        g_norm[e] = 1.0f / (float)(c > 1 ? c : 1);
    }
}

// ---------------- weight image prep (Wt[n][k], padded rows) ------------------
__global__ void prep_w1(const float* __restrict__ W, const float* __restrict__ root) {
    int e = blockIdx.x * blockDim.x + threadIdx.x;
    if (e >= 5 * 128 * 128) return;
    int batch = e / 16384, r = e % 16384;
    int k = r / 128, n = r % 128;
    float v = (batch < 4) ? W[(size_t)batch * 16384 + k * 128 + n] : root[k * 128 + n];
    __nv_bfloat16 hi = __float2bfloat16(v);
    __nv_bfloat16 lo = __float2bfloat16(v - __bfloat162float(hi));
    size_t off = (size_t)batch * IMG_BYTES + (size_t)n * ROW_BYTES + (size_t)k * 2;
    *(__nv_bfloat16*)((char*)g_B1hi + off) = hi;
    *(__nv_bfloat16*)((char*)g_B1lo + off) = lo;
}
__global__ void prep_w2(const float* __restrict__ W, const float* __restrict__ root) {
    int e = blockIdx.x * blockDim.x + threadIdx.x;
    if (e >= 5 * 128 * 96) return;
    int batch = e / 12288, r = e % 12288;
    int k = r / 96, n = r % 96;
    float v = (batch < 4) ? W[(size_t)batch * 12288 + k * 96 + n] : root[k * 96 + n];
    __nv_bfloat16 hi = __float2bfloat16(v);
    __nv_bfloat16 lo = __float2bfloat16(v - __bfloat162float(hi));
    size_t off = (size_t)batch * IMG_BYTES + (size_t)n * ROW_BYTES + (size_t)k * 2;
    *(__nv_bfloat16*)((char*)g_B2hi + off) = hi;
    *(__nv_bfloat16*)((char*)g_B2lo + off) = lo;
}

// ---------------- A-image conversion (x or relu(out1) -> hi/lo images) -------
template <int SRC>  // 0: external x, 1: relu(g_out1)
__global__ void convert_A(const float* __restrict__ xext) {
    int t = blockIdx.x * blockDim.x + threadIdx.x;
    if (t >= M_PAD * 16) return;
    int m = t >> 4, k8 = t & 15;
    float v[8];
    if (m < N_NODES) {
        const float* src = (SRC == 0) ? xext : g_out1;
        const float4* p = (const float4*)(src + (size_t)m * 128 + k8 * 8);
        float4 a = p[0], b = p[1];
        v[0]=a.x; v[1]=a.y; v[2]=a.z; v[3]=a.w; v[4]=b.x; v[5]=b.y; v[6]=b.z; v[7]=b.w;
        if (SRC == 1) {
#pragma unroll
            for (int i = 0; i < 8; i++) v[i] = fmaxf(v[i], 0.f);
        }
    } else {
#pragma unroll
        for (int i = 0; i < 8; i++) v[i] = 0.f;
    }
    unsigned short h[8], l[8];
#pragma unroll
    for (int i = 0; i < 8; i++) {
        __nv_bfloat16 hi = __float2bfloat16(v[i]);
        __nv_bfloat16 lo = __float2bfloat16(v[i] - __bfloat162float(hi));
        h[i] = *(unsigned short*)&hi; l[i] = *(unsigned short*)&lo;
    }
    int tile = m >> 7, row = m & 127;
    size_t base = (size_t)tile * IMG_BYTES + (size_t)row * ROW_BYTES + (size_t)k8 * 16;
    *(uint4*)((char*)g_Ahi + base) = *(uint4*)h;
    *(uint4*)((char*)g_Alo + base) = *(uint4*)l;
}

// ---------------- mma.sync GEMM ----------------------------------------------
// grid = (5 batches, N_TILES tiles); batch 4 = root (+bias)
// CTA 128x128 tile, 512 threads, 16 warps 4x4, warp tile 32x32.
// 3-term bf16 split accumulated in fp32: Ah*Bh + Ah*Bl + Al*Bh.
#define SMEM_BYTES (4 * IMG_BYTES)

template <int DOUT>
__global__ __launch_bounds__(512, 1)
void gemm_mma(const float* __restrict__ bias, float* __restrict__ out_ext)
{
    extern __shared__ char smem[];
    int tid = threadIdx.x;
    int wid = tid >> 5, lane = tid & 31;
    int batch = blockIdx.x;
    int tile  = blockIdx.y;
    bool isRoot = (batch == 4);

    // flat copies of pre-built images
    {
        const uint4* ahi = g_Ahi + (size_t)tile * IMG_U4;
        const uint4* alo = g_Alo + (size_t)tile * IMG_U4;
        const uint4* bhi = (DOUT == 128 ? g_B1hi : g_B2hi) + (size_t)batch * IMG_U4;
        const uint4* blo = (DOUT == 128 ? g_B1lo : g_B2lo) + (size_t)batch * IMG_U4;
        uint4* s0 = (uint4*)smem;
        uint4* s1 = (uint4*)(smem + IMG_BYTES);
        uint4* s2 = (uint4*)(smem + 2 * IMG_BYTES);
        uint4* s3 = (uint4*)(smem + 3 * IMG_BYTES);
        for (int i = tid; i < IMG_U4; i += 512) {
            s0[i] = ahi[i]; s1[i] = alo[i]; s2[i] = bhi[i]; s3[i] = blo[i];
        }
    }
    __syncthreads();

    int warp_m = (wid & 3) * 32;
    int warp_n = (wid >> 2) * 32;
    uint32_t sb = smem_u32(smem);

    // per-lane ldmatrix addresses
    // A x4: lanes 0-15 -> rows m0..15 @ k-lo chunk, lanes 16-31 -> same rows @ k-hi
    uint32_t aoff = (uint32_t)(warp_m + (lane & 15)) * ROW_BYTES + ((lane >> 4) & 1) * 16;
    // B x4: matrices (n0-7,klo)(n0-7,khi)(n8-15,klo)(n8-15,khi)
    uint32_t boff = (uint32_t)(warp_n + (lane & 7) + ((lane >> 4) & 1) * 8) * ROW_BYTES
                  + ((lane >> 3) & 1) * 16;

    uint32_t aA[2][2], bA[2][2];   // [split][frag]
#pragma unroll
    for (int s = 0; s < 2; s++) {
#pragma unroll
        for (int i = 0; i < 2; i++)
            aA[s][i] = sb + s * IMG_BYTES + aoff + i * 16 * ROW_BYTES;
#pragma unroll
        for (int jj = 0; jj < 2; jj++)
            bA[s][jj] = sb + (2 + s) * IMG_BYTES + boff + jj * 16 * ROW_BYTES;
    }

    float acc[2][4][4];
#pragma unroll
    for (int i = 0; i < 2; i++)
#pragma unroll
        for (int j = 0; j < 4; j++)
#pragma unroll
            for (int q = 0; q < 4; q++) acc[i][j][q] = 0.f;

#pragma unroll
    for (int kk = 0; kk < 8; kk++) {
        uint32_t ah[2][4], al[2][4], bh[2][4], bl[2][4];
#pragma unroll
        for (int i = 0; i < 2; i++) {
            LDSM4(ah[i], aA[0][i]);
            LDSM4(al[i], aA[1][i]);
            aA[0][i] += 32; aA[1][i] += 32;
        }
#pragma unroll
        for (int jj = 0; jj < 2; jj++) {
            LDSM4(bh[jj], bA[0][jj]);
            LDSM4(bl[jj], bA[1][jj]);
            bA[0][jj] += 32; bA[1][jj] += 32;
        }
#pragma unroll
        for (int i = 0; i < 2; i++) {
#pragma unroll
            for (int j = 0; j < 4; j++) {
                int jj = j >> 1, q = (j & 1) * 2;
                MMA16816(acc[i][j], ah[i], bh[jj][q], bh[jj][q + 1]);
                MMA16816(acc[i][j], ah[i], bl[jj][q], bl[jj][q + 1]);
                MMA16816(acc[i][j], al[i], bh[jj][q], bh[jj][q + 1]);
            }
        }
    }

    // epilogue: c frag lane map: rows (lane>>2, +8), cols (lane&3)*2 (+1)
    float* Hbuf = (DOUT == 128) ? g_H1 : g_H2;
    float* Obuf = (DOUT == 128) ? g_out1 : out_ext;
#pragma unroll
    for (int i = 0; i < 2; i++) {
        int row0 = tile * 128 + warp_m + i * 16 + (lane >> 2);
#pragma unroll
        for (int j = 0; j < 4; j++) {
            int col = warp_n + j * 8 + (lane & 3) * 2;
            if (col >= DOUT) continue;
            float2 v0 = make_float2(acc[i][j][0], acc[i][j][1]);
            float2 v1 = make_float2(acc[i][j][2], acc[i][j][3]);
            if (isRoot) {
                float b0 = bias[col], b1 = bias[col + 1];
                v0.x += b0; v0.y += b1; v1.x += b0; v1.y += b1;
            }
            if (row0 < N_NODES) {
                float* dst = isRoot ? (Obuf + (size_t)row0 * DOUT)
                                    : (Hbuf + ((size_t)batch * N_NODES + row0) * DOUT);
                *(float2*)(dst + col) = v0;
            }
            if (row0 + 8 < N_NODES) {
                float* dst = isRoot ? (Obuf + (size_t)(row0 + 8) * DOUT)
                                    : (Hbuf + ((size_t)batch * N_NODES + row0 + 8) * DOUT);
                *(float2*)(dst + col) = v1;
            }
        }
    }
}

// ---------------- edge scatter: one warp per edge, red.global.add.v4 ---------
template <int DOUT>
__global__ void scatter_kernel(const int* __restrict__ ei, const int* __restrict__ et,
                               float* __restrict__ out_ext)
{
    int warp = blockIdx.x * (blockDim.x >> 5) + (threadIdx.x >> 5);
    int lane = threadIdx.x & 31;
    if (warp >= N_EDGES) return;

    const float* H = (DOUT == 128) ? g_H1 : g_H2;
    float* out = (DOUT == 128) ? g_out1 : out_ext;

    int src = ei[warp];
    int dst = ei[N_EDGES + warp];
    int t   = et[warp];
    float nm = g_norm[warp];

    if (lane < DOUT / 4) {
        const float4* hp = (const float4*)(H + ((size_t)t * N_NODES + src) * DOUT);
        float4 v = hp[lane];
        float* op = out + (size_t)dst * DOUT + lane * 4;
        asm volatile("red.global.add.v4.f32 [%0], {%1,%2,%3,%4};"
                     :: "l"(op), "f"(v.x * nm), "f"(v.y * nm),
                        "f"(v.z * nm), "f"(v.w * nm)
                     : "memory");
    }
}

// ---------------- launch -----------------------------------------------------
extern "C" void kernel_launch(void* const* d_in, const int* in_sizes, int n_in,
                              void* d_out, int out_size)
{
    const float* x     = (const float*)d_in[0];
    const int*   ei    = (const int*)d_in[1];
    const int*   et    = (const int*)d_in[2];
    const float* W1    = (const float*)d_in[3];
    const float* root1 = (const float*)d_in[4];
    const float* b1    = (const float*)d_in[5];
    const float* W2    = (const float*)d_in[6];
    const float* root2 = (const float*)d_in[7];
    const float* b2    = (const float*)d_in[8];
    float* out = (float*)d_out;

    cudaFuncSetAttribute(gemm_mma<128>, cudaFuncAttributeMaxDynamicSharedMemorySize, SMEM_BYTES);
    cudaFuncSetAttribute(gemm_mma<96>,  cudaFuncAttributeMaxDynamicSharedMemorySize, SMEM_BYTES);

    zero_cnt_kernel<<<(N_NODES * N_REL + 255) / 256, 256>>>();
    count_kernel<<<(N_EDGES + 255) / 256, 256>>>(ei, et);
    norm_kernel<<<(N_EDGES + 255) / 256, 256>>>(ei, et);

    prep_w1<<<(5 * 128 * 128 + 255) / 256, 256>>>(W1, root1);
    prep_w2<<<(5 * 128 * 96 + 255) / 256, 256>>>(W2, root2);
    convert_A<0><<<(M_PAD * 16 + 255) / 256, 256>>>(x);

    // layer 1
    gemm_mma<128><<<dim3(5, N_TILES), 512, SMEM_BYTES>>>(b1, nullptr);
    scatter_kernel<D_IN><<<(N_EDGES + 7) / 8, 256>>>(ei, et, nullptr);
    convert_A<1><<<(M_PAD * 16 + 255) / 256, 256>>>(nullptr);   // relu + split of out1

    // layer 2
    gemm_mma<96><<<dim3(5, N_TILES), 512, SMEM_BYTES>>>(b2, out);
    scatter_kernel<D_OUT><<<(N_EDGES + 7) / 8, 256>>>(ei, et, out);
}